// round 3
// baseline (speedup 1.0000x reference)
#include <cuda_runtime.h>
#include <cuda_bf16.h>
#include <cstdint>

#define NN 100000
#define EE 1600000

// ---------------- scratch (static device globals; no allocation) ----------
__device__ int   g_is64;           // 1 if edge_index is int64, 0 if int32
__device__ int   g_orhi;           // OR of sampled high/odd words
__device__ int   g_cnt[NN];
__device__ int   g_rowoff[NN + 1];
__device__ int   g_cursor[NN];
__device__ float g_dinv[NN];
__device__ int   g_col[EE];
__device__ float g_w[EE];
__device__ float g_bufA[(size_t)NN * 64];   // agg outputs (gemm inputs)
__device__ float g_bufB[(size_t)NN * 64];   // gemm outputs (agg inputs)

// ---------------- dtype detection --------------------------------------
// If data is int64 (LE), words at odd int32 positions are the high halves of
// nonneg ids < 2^31 -> all zero. If data is int32, those words are node ids
// (random in [0,N)); OR over 4096 of them is ~surely nonzero.
__global__ void k_detect(const int* __restrict__ ei32) {
    int tid = threadIdx.x;
    if (tid == 0) g_orhi = 0;
    __syncthreads();
    int acc = 0;
    for (int i = tid; i < 4096; i += blockDim.x)
        acc |= ei32[2 * i + 1];
    // warp + block reduce via atomic (tiny)
    atomicOr(&g_orhi, acc);
    __syncthreads();
    if (tid == 0) g_is64 = (g_orhi == 0) ? 1 : 0;
}

__device__ __forceinline__ int edge_id(const void* ei, size_t idx) {
    if (g_is64) return (int)((const long long*)ei)[idx];
    return ((const int*)ei)[idx];
}

// ---------------- CSR build --------------------------------------------
__global__ void k_zero_cnt(int n) {
    int i = blockIdx.x * blockDim.x + threadIdx.x;
    if (i < n) g_cnt[i] = 0;
}

__global__ void k_count(const void* __restrict__ ei, int E) {
    int e = blockIdx.x * blockDim.x + threadIdx.x;
    if (e < E) {
        int d = edge_id(ei, (size_t)E + e);
        atomicAdd(&g_cnt[d], 1);
    }
}

__global__ void k_dinv(int n) {
    int i = blockIdx.x * blockDim.x + threadIdx.x;
    if (i < n) g_dinv[i] = rsqrtf((float)(g_cnt[i] + 1));  // +1 self loop
}

// single-block exclusive scan of g_cnt -> g_rowoff / g_cursor
__global__ void k_scan(int n) {
    __shared__ int wsum[32];
    __shared__ int s_carry;
    int tid = threadIdx.x, lane = tid & 31, wid = tid >> 5;
    if (tid == 0) { s_carry = 0; g_rowoff[0] = 0; }
    __syncthreads();
    for (int base = 0; base < n; base += 1024) {
        int i = base + tid;
        int v = (i < n) ? g_cnt[i] : 0;
        int x = v;
        #pragma unroll
        for (int d = 1; d < 32; d <<= 1) {
            int t = __shfl_up_sync(0xffffffffu, x, d);
            if (lane >= d) x += t;
        }
        if (lane == 31) wsum[wid] = x;
        __syncthreads();
        if (wid == 0) {
            int y = wsum[lane];
            #pragma unroll
            for (int d = 1; d < 32; d <<= 1) {
                int t = __shfl_up_sync(0xffffffffu, y, d);
                if (lane >= d) y += t;
            }
            wsum[lane] = y;
        }
        __syncthreads();
        int warpoff = (wid > 0) ? wsum[wid - 1] : 0;
        int incl = x + warpoff + s_carry;
        if (i < n) {
            g_rowoff[i + 1] = incl;
            g_cursor[i]     = incl - v;
        }
        __syncthreads();
        if (tid == 0) s_carry += wsum[31];
        __syncthreads();
    }
}

__global__ void k_fill(const void* __restrict__ ei, int E) {
    int e = blockIdx.x * blockDim.x + threadIdx.x;
    if (e < E) {
        int s = edge_id(ei, (size_t)e);
        int d = edge_id(ei, (size_t)E + e);
        int j = atomicAdd(&g_cursor[d], 1);
        g_col[j] = s;
        g_w[j]   = g_dinv[s] * g_dinv[d];
    }
}

// ---------------- dense transform: g_bufB = X @ W -----------------------
// X is either the external pointer (x_ext, when use_ext) or g_bufA.
template <int DOUT, int R>
__global__ void k_gemm(const float* __restrict__ x_ext, int use_ext,
                       const float* __restrict__ Wg, int n) {
    constexpr int COLG = DOUT / 4;        // float4 col groups
    constexpr int TY   = 256 / COLG;      // row groups per block
    constexpr int ROWS = TY * R;          // rows per block tile
    __shared__ __align__(16) float Ws[64 * DOUT];
    __shared__ float Xs[ROWS][65];

    const float* __restrict__ X = use_ext ? x_ext : (const float*)g_bufA;
    float* __restrict__ Y = g_bufB;

    int tid = threadIdx.x;
    for (int i = tid; i < 64 * DOUT; i += 256) Ws[i] = Wg[i];

    int row0 = blockIdx.x * ROWS;
    for (int i = tid; i < ROWS * 64; i += 256) {
        int r = i >> 6, k = i & 63;
        int row = row0 + r;
        Xs[r][k] = (row < n) ? X[(size_t)row * 64 + k] : 0.f;
    }
    __syncthreads();

    int tx = tid % COLG;
    int ty = tid / COLG;
    float acc[R][4];
    #pragma unroll
    for (int r = 0; r < R; r++)
        #pragma unroll
        for (int c = 0; c < 4; c++) acc[r][c] = 0.f;

    #pragma unroll
    for (int k = 0; k < 64; k++) {
        float4 w4 = *(const float4*)&Ws[k * DOUT + tx * 4];
        #pragma unroll
        for (int r = 0; r < R; r++) {
            float xv = Xs[ty * R + r][k];
            acc[r][0] += xv * w4.x;
            acc[r][1] += xv * w4.y;
            acc[r][2] += xv * w4.z;
            acc[r][3] += xv * w4.w;
        }
    }

    #pragma unroll
    for (int r = 0; r < R; r++) {
        int row = row0 + ty * R + r;
        if (row < n) {
            float4 o = make_float4(acc[r][0], acc[r][1], acc[r][2], acc[r][3]);
            *(float4*)&Y[(size_t)row * DOUT + tx * 4] = o;
        }
    }
}

// ---------------- aggregation (gather over CSR) + bias (+relu) ----------
// one warp per node, 2 features per lane (D=64). Reads g_bufB, writes g_bufA.
__global__ void k_agg64(const float* __restrict__ bias, int n, int relu) {
    int warp = (blockIdx.x * blockDim.x + threadIdx.x) >> 5;
    int lane = threadIdx.x & 31;
    if (warp >= n) return;
    int beg = g_rowoff[warp];
    int end = g_rowoff[warp + 1];
    const float2* __restrict__ H2 = (const float2*)g_bufB;

    float  di = g_dinv[warp];
    float2 hv = H2[(size_t)warp * 32 + lane];
    float  dd = di * di;
    float2 acc  = make_float2(dd * hv.x, dd * hv.y);
    float2 acc2 = make_float2(0.f, 0.f);

    int j = beg;
    for (; j + 1 < end; j += 2) {
        int   c0 = g_col[j],     c1 = g_col[j + 1];
        float w0 = g_w[j],       w1 = g_w[j + 1];
        float2 v0 = H2[(size_t)c0 * 32 + lane];
        float2 v1 = H2[(size_t)c1 * 32 + lane];
        acc.x  += w0 * v0.x;  acc.y  += w0 * v0.y;
        acc2.x += w1 * v1.x;  acc2.y += w1 * v1.y;
    }
    if (j < end) {
        int   c0 = g_col[j];
        float w0 = g_w[j];
        float2 v0 = H2[(size_t)c0 * 32 + lane];
        acc.x += w0 * v0.x;  acc.y += w0 * v0.y;
    }
    acc.x += acc2.x;  acc.y += acc2.y;

    float2 b2 = ((const float2*)bias)[lane];
    acc.x += b2.x;  acc.y += b2.y;
    if (relu) { acc.x = fmaxf(acc.x, 0.f); acc.y = fmaxf(acc.y, 0.f); }
    ((float2*)g_bufA)[(size_t)warp * 32 + lane] = acc;
}

// D=16 final layer (no relu): reads g_bufB, writes external out.
__global__ void k_agg16(const float* __restrict__ bias, float* __restrict__ out, int n) {
    int warp = (blockIdx.x * blockDim.x + threadIdx.x) >> 5;
    int lane = threadIdx.x & 31;
    if (warp >= n) return;
    int beg = g_rowoff[warp];
    int end = g_rowoff[warp + 1];
    const float* __restrict__ H = (const float*)g_bufB;

    float di  = g_dinv[warp];
    float acc = 0.f, acc2 = 0.f;
    if (lane < 16) acc = di * di * H[(size_t)warp * 16 + lane];

    int j = beg;
    for (; j + 1 < end; j += 2) {
        int   c0 = g_col[j],  c1 = g_col[j + 1];
        float w0 = g_w[j],    w1 = g_w[j + 1];
        float v0 = 0.f, v1 = 0.f;
        if (lane < 16) {
            v0 = H[(size_t)c0 * 16 + lane];
            v1 = H[(size_t)c1 * 16 + lane];
        }
        acc  += w0 * v0;
        acc2 += w1 * v1;
    }
    if (j < end) {
        int   c0 = g_col[j];
        float w0 = g_w[j];
        float v0 = (lane < 16) ? H[(size_t)c0 * 16 + lane] : 0.f;
        acc += w0 * v0;
    }
    acc += acc2;
    if (lane < 16)
        out[(size_t)warp * 16 + lane] = acc + bias[lane];
}

// ---------------- launch ------------------------------------------------
extern "C" void kernel_launch(void* const* d_in, const int* in_sizes, int n_in,
                              void* d_out, int out_size) {
    const float* x  = (const float*)d_in[0];
    const void*  ei = d_in[1];
    const float* W1 = (const float*)d_in[2];  const float* b1 = (const float*)d_in[3];
    const float* W2 = (const float*)d_in[4];  const float* b2 = (const float*)d_in[5];
    const float* W3 = (const float*)d_in[6];  const float* b3 = (const float*)d_in[7];
    const float* W4 = (const float*)d_in[8];  const float* b4 = (const float*)d_in[9];
    float* out = (float*)d_out;

    int n = in_sizes[0] / 64;   // 100000
    int E = in_sizes[1] / 2;    // 1600000 (element count is dtype-independent)

    int nb_n = (n + 255) / 256;
    int nb_e = (E + 255) / 256;
    int nb_g = (n + 63) / 64;                 // gemm: 64 rows / block
    int nb_a = ((n * 32) + 255) / 256;        // agg: warp per node

    // dtype detection + CSR build
    k_detect<<<1, 256>>>((const int*)ei);
    k_zero_cnt<<<nb_n, 256>>>(n);
    k_count<<<nb_e, 256>>>(ei, E);
    k_dinv<<<nb_n, 256>>>(n);
    k_scan<<<1, 1024>>>(n);
    k_fill<<<nb_e, 256>>>(ei, E);

    // layer 1
    k_gemm<64, 4><<<nb_g, 256>>>(x, 1, W1, n);
    k_agg64<<<nb_a, 256>>>(b1, n, 1);
    // layer 2
    k_gemm<64, 4><<<nb_g, 256>>>(x, 0, W2, n);
    k_agg64<<<nb_a, 256>>>(b2, n, 1);
    // layer 3
    k_gemm<64, 4><<<nb_g, 256>>>(x, 0, W3, n);
    k_agg64<<<nb_a, 256>>>(b3, n, 1);
    // layer 4 (D_OUT = 16, no relu)
    k_gemm<16, 1><<<nb_g, 256>>>(x, 0, W4, n);
    k_agg16<<<nb_a, 256>>>(b4, out, n);
}

// round 4
// speedup vs baseline: 1.5311x; 1.5311x over previous
#include <cuda_runtime.h>
#include <cuda_fp16.h>
#include <cuda_bf16.h>
#include <cstdint>

#define NN 100000
#define EE 1600000

// ---------------- scratch (static device globals; no allocation) ----------
__device__ int   g_is64;           // 1 if edge_index is int64, 0 if int32
__device__ int   g_orhi;
__device__ int   g_cnt[NN];
__device__ int   g_rowoff[NN + 1];
__device__ int   g_cursor[NN];
__device__ float g_dinv[NN];
__device__ int   g_bsum[128];
__device__ int   g_boff[128];
__device__ __align__(16) long long g_ew[EE];           // packed (w<<32 | col)
__device__ __align__(16) __half    g_h16[(size_t)NN * 64];  // gemm out (fp16)
__device__ __align__(16) float     g_bufA[(size_t)NN * 64]; // agg out (gemm in)

// ---------------- small helpers ----------------------------------------
__device__ __forceinline__ void ffma2(unsigned long long& acc,
                                      unsigned long long a,
                                      unsigned long long b) {
    asm("fma.rn.f32x2 %0, %1, %2, %0;" : "+l"(acc) : "l"(a), "l"(b));
}
__device__ __forceinline__ unsigned long long pack_dup(float x) {
    unsigned long long r;
    asm("mov.b64 %0, {%1, %1};" : "=l"(r) : "f"(x));
    return r;
}
__device__ __forceinline__ float2 unpack2(unsigned long long v) {
    float2 f;
    asm("mov.b64 {%0, %1}, %2;" : "=f"(f.x), "=f"(f.y) : "l"(v));
    return f;
}

// ---------------- dtype detection --------------------------------------
__global__ void k_detect(const int* __restrict__ ei32) {
    int tid = threadIdx.x;
    if (tid == 0) g_orhi = 0;
    __syncthreads();
    int acc = 0;
    for (int i = tid; i < 4096; i += blockDim.x)
        acc |= ei32[2 * i + 1];
    atomicOr(&g_orhi, acc);
    __syncthreads();
    if (tid == 0) g_is64 = (g_orhi == 0) ? 1 : 0;
}

__device__ __forceinline__ int edge_id(const void* ei, size_t idx) {
    if (g_is64) return (int)((const long long*)ei)[idx];
    return ((const int*)ei)[idx];
}

// ---------------- CSR build --------------------------------------------
__global__ void k_zero_cnt(int n) {
    int i = blockIdx.x * blockDim.x + threadIdx.x;
    if (i < n) g_cnt[i] = 0;
}

__global__ void k_count(const void* __restrict__ ei, int E) {
    int e = blockIdx.x * blockDim.x + threadIdx.x;
    if (e < E) {
        int d = edge_id(ei, (size_t)E + e);
        atomicAdd(&g_cnt[d], 1);
    }
}

// pass 1: per-block inclusive scan of cnt (1024/block), dinv fused
__global__ void k_scan1(int n) {
    __shared__ int wsum[32];
    int tid = threadIdx.x, lane = tid & 31, wid = tid >> 5;
    int i = blockIdx.x * 1024 + tid;
    int v = (i < n) ? g_cnt[i] : 0;
    if (i < n) g_dinv[i] = rsqrtf((float)(v + 1));  // +1 self loop
    int x = v;
    #pragma unroll
    for (int d = 1; d < 32; d <<= 1) {
        int t = __shfl_up_sync(0xffffffffu, x, d);
        if (lane >= d) x += t;
    }
    if (lane == 31) wsum[wid] = x;
    __syncthreads();
    if (wid == 0) {
        int y = wsum[lane];
        #pragma unroll
        for (int d = 1; d < 32; d <<= 1) {
            int t = __shfl_up_sync(0xffffffffu, y, d);
            if (lane >= d) y += t;
        }
        wsum[lane] = y;
    }
    __syncthreads();
    int incl = x + ((wid > 0) ? wsum[wid - 1] : 0);
    if (i < n) g_cursor[i] = incl;             // block-local inclusive (temp)
    if (tid == 1023) g_bsum[blockIdx.x] = incl;
}

// pass 2: exclusive scan of <=128 block sums (single block, 128 threads)
__global__ void k_scan2(int nb) {
    __shared__ int ws[4];
    __shared__ int woff[4];
    int tid = threadIdx.x, lane = tid & 31, wid = tid >> 5;
    int v = (tid < nb) ? g_bsum[tid] : 0;
    int x = v;
    #pragma unroll
    for (int d = 1; d < 32; d <<= 1) {
        int t = __shfl_up_sync(0xffffffffu, x, d);
        if (lane >= d) x += t;
    }
    if (lane == 31) ws[wid] = x;
    __syncthreads();
    if (tid == 0) {
        int s = 0;
        #pragma unroll
        for (int w = 0; w < 4; w++) { woff[w] = s; s += ws[w]; }
    }
    __syncthreads();
    if (tid < nb) g_boff[tid] = x - v + woff[wid];
}

// pass 3: add block offsets -> rowoff / cursor
__global__ void k_scan3(int n) {
    int i = blockIdx.x * blockDim.x + threadIdx.x;
    if (i < n) {
        int incl = g_cursor[i] + g_boff[i >> 10];
        g_rowoff[i + 1] = incl;
        g_cursor[i]     = incl - g_cnt[i];
    }
    if (i == 0) g_rowoff[0] = 0;
}

__global__ void k_fill(const void* __restrict__ ei, int E) {
    int e = blockIdx.x * blockDim.x + threadIdx.x;
    if (e < E) {
        int s = edge_id(ei, (size_t)e);
        int d = edge_id(ei, (size_t)E + e);
        int j = atomicAdd(&g_cursor[d], 1);
        float w = g_dinv[s] * g_dinv[d];
        g_ew[j] = ((long long)((unsigned long long)__float_as_uint(w) << 32))
                | (long long)(unsigned)s;
    }
}

// ---------------- dense transform: g_h16 = (X @ W) as fp16 --------------
template <int DOUT, int R>
__global__ void k_gemm(const float* __restrict__ x_ext, int use_ext,
                       const float* __restrict__ Wg, int n) {
    constexpr int COLG = DOUT / 4;        // float4 col groups
    constexpr int TY   = 256 / COLG;      // row groups per block
    constexpr int ROWS = TY * R;          // rows per block tile (=64)
    __shared__ __align__(16) float Ws[64 * DOUT];
    __shared__ __align__(16) float Xs[ROWS][64];

    const float* __restrict__ X = use_ext ? x_ext : (const float*)g_bufA;
    __half2* __restrict__ Y = (__half2*)g_h16;

    int tid = threadIdx.x;
    for (int i = tid; i < 64 * DOUT / 4; i += 256)
        ((float4*)Ws)[i] = ((const float4*)Wg)[i];

    int row0 = blockIdx.x * ROWS;
    for (int i = tid; i < ROWS * 16; i += 256) {
        int r = i >> 4, kq = i & 15;
        int row = row0 + r;
        float4 v = (row < n) ? ((const float4*)X)[(size_t)row * 16 + kq]
                             : make_float4(0.f, 0.f, 0.f, 0.f);
        *(float4*)&Xs[r][kq * 4] = v;
    }
    __syncthreads();

    int tx = tid % COLG;
    int ty = tid / COLG;
    unsigned long long a01[R], a23[R];
    #pragma unroll
    for (int r = 0; r < R; r++) { a01[r] = 0ull; a23[r] = 0ull; }

    #pragma unroll
    for (int k = 0; k < 64; k++) {
        ulonglong2 wv = *(const ulonglong2*)&Ws[k * DOUT + tx * 4];
        #pragma unroll
        for (int r = 0; r < R; r++) {
            unsigned long long xx = pack_dup(Xs[ty * R + r][k]);
            ffma2(a01[r], xx, wv.x);
            ffma2(a23[r], xx, wv.y);
        }
    }

    #pragma unroll
    for (int r = 0; r < R; r++) {
        int row = row0 + ty * R + r;
        if (row < n) {
            float2 f01 = unpack2(a01[r]);
            float2 f23 = unpack2(a23[r]);
            Y[(size_t)row * (DOUT / 2) + tx * 2]     = __floats2half2_rn(f01.x, f01.y);
            Y[(size_t)row * (DOUT / 2) + tx * 2 + 1] = __floats2half2_rn(f23.x, f23.y);
        }
    }
}

// ---------------- aggregation (gather over CSR) + bias (+relu) ----------
// one warp per node, 2 features (half2) per lane. Reads g_h16, writes g_bufA.
__global__ void k_agg64(const float* __restrict__ bias, int n, int relu) {
    int warp = (blockIdx.x * blockDim.x + threadIdx.x) >> 5;
    int lane = threadIdx.x & 31;
    if (warp >= n) return;
    int beg = g_rowoff[warp];
    int end = g_rowoff[warp + 1];
    const __half2* __restrict__ H = (const __half2*)g_h16;

    float di = g_dinv[warp];
    float dd = di * di;
    float2 hv = __half22float2(H[(size_t)warp * 32 + lane]);
    float2 a0 = make_float2(dd * hv.x, dd * hv.y);
    float2 a1 = make_float2(0.f, 0.f);
    float2 a2 = make_float2(0.f, 0.f);
    float2 a3 = make_float2(0.f, 0.f);

    int j = beg;
    for (; j + 3 < end; j += 4) {
        long long e0 = g_ew[j],     e1 = g_ew[j + 1];
        long long e2 = g_ew[j + 2], e3 = g_ew[j + 3];
        int c0 = (int)(unsigned)(e0 & 0xffffffffLL);
        int c1 = (int)(unsigned)(e1 & 0xffffffffLL);
        int c2 = (int)(unsigned)(e2 & 0xffffffffLL);
        int c3 = (int)(unsigned)(e3 & 0xffffffffLL);
        float w0 = __uint_as_float((unsigned)((unsigned long long)e0 >> 32));
        float w1 = __uint_as_float((unsigned)((unsigned long long)e1 >> 32));
        float w2 = __uint_as_float((unsigned)((unsigned long long)e2 >> 32));
        float w3 = __uint_as_float((unsigned)((unsigned long long)e3 >> 32));
        float2 v0 = __half22float2(H[(size_t)c0 * 32 + lane]);
        float2 v1 = __half22float2(H[(size_t)c1 * 32 + lane]);
        float2 v2 = __half22float2(H[(size_t)c2 * 32 + lane]);
        float2 v3 = __half22float2(H[(size_t)c3 * 32 + lane]);
        a0.x += w0 * v0.x;  a0.y += w0 * v0.y;
        a1.x += w1 * v1.x;  a1.y += w1 * v1.y;
        a2.x += w2 * v2.x;  a2.y += w2 * v2.y;
        a3.x += w3 * v3.x;  a3.y += w3 * v3.y;
    }
    for (; j < end; ++j) {
        long long e = g_ew[j];
        int   c = (int)(unsigned)(e & 0xffffffffLL);
        float w = __uint_as_float((unsigned)((unsigned long long)e >> 32));
        float2 v = __half22float2(H[(size_t)c * 32 + lane]);
        a0.x += w * v.x;  a0.y += w * v.y;
    }
    a0.x += a1.x + a2.x + a3.x;
    a0.y += a1.y + a2.y + a3.y;

    float2 b2 = ((const float2*)bias)[lane];
    float ox = a0.x + b2.x, oy = a0.y + b2.y;
    if (relu) { ox = fmaxf(ox, 0.f); oy = fmaxf(oy, 0.f); }
    ((float2*)g_bufA)[(size_t)warp * 32 + lane] = make_float2(ox, oy);
}

// D=16 final layer: warp per node, 4 edges in flight (8 lanes each own a half2)
__global__ void k_agg16(const float* __restrict__ bias, float* __restrict__ out, int n) {
    int warp = (blockIdx.x * blockDim.x + threadIdx.x) >> 5;
    int lane = threadIdx.x & 31;
    if (warp >= n) return;
    int eg = lane >> 3;        // edge group 0..3
    int p  = lane & 7;         // feature pair 0..7
    int beg = g_rowoff[warp];
    int end = g_rowoff[warp + 1];
    const __half2* __restrict__ H = (const __half2*)g_h16;

    float di = g_dinv[warp];
    float dd = di * di;
    float2 acc = make_float2(0.f, 0.f);
    if (eg == 0) {
        float2 hv = __half22float2(H[(size_t)warp * 8 + p]);
        acc.x = dd * hv.x;  acc.y = dd * hv.y;
    }
    for (int j = beg + eg; j < end; j += 4) {
        long long e = g_ew[j];
        int   c = (int)(unsigned)(e & 0xffffffffLL);
        float w = __uint_as_float((unsigned)((unsigned long long)e >> 32));
        float2 v = __half22float2(H[(size_t)c * 8 + p]);
        acc.x += w * v.x;  acc.y += w * v.y;
    }
    acc.x += __shfl_xor_sync(0xffffffffu, acc.x, 8);
    acc.x += __shfl_xor_sync(0xffffffffu, acc.x, 16);
    acc.y += __shfl_xor_sync(0xffffffffu, acc.y, 8);
    acc.y += __shfl_xor_sync(0xffffffffu, acc.y, 16);

    if (lane < 8) {
        float2 b2 = ((const float2*)bias)[p];
        ((float2*)out)[(size_t)warp * 8 + p] = make_float2(acc.x + b2.x, acc.y + b2.y);
    }
}

// ---------------- launch ------------------------------------------------
extern "C" void kernel_launch(void* const* d_in, const int* in_sizes, int n_in,
                              void* d_out, int out_size) {
    const float* x  = (const float*)d_in[0];
    const void*  ei = d_in[1];
    const float* W1 = (const float*)d_in[2];  const float* b1 = (const float*)d_in[3];
    const float* W2 = (const float*)d_in[4];  const float* b2 = (const float*)d_in[5];
    const float* W3 = (const float*)d_in[6];  const float* b3 = (const float*)d_in[7];
    const float* W4 = (const float*)d_in[8];  const float* b4 = (const float*)d_in[9];
    float* out = (float*)d_out;

    int n = in_sizes[0] / 64;   // 100000
    int E = in_sizes[1] / 2;    // 1600000

    int nb_n  = (n + 255) / 256;
    int nb_e  = (E + 255) / 256;
    int nb_s1 = (n + 1023) / 1024;            // <=128
    int nb_g  = (n + 63) / 64;                // gemm: 64 rows / block
    int nb_a  = ((n * 32) + 255) / 256;       // agg: warp per node

    // dtype detection + CSR build
    k_detect<<<1, 256>>>((const int*)ei);
    k_zero_cnt<<<nb_n, 256>>>(n);
    k_count<<<nb_e, 256>>>(ei, E);
    k_scan1<<<nb_s1, 1024>>>(n);
    k_scan2<<<1, 128>>>(nb_s1);
    k_scan3<<<nb_n, 256>>>(n);
    k_fill<<<nb_e, 256>>>(ei, E);

    // layer 1
    k_gemm<64, 4><<<nb_g, 256>>>(x, 1, W1, n);
    k_agg64<<<nb_a, 256>>>(b1, n, 1);
    // layer 2
    k_gemm<64, 4><<<nb_g, 256>>>(x, 0, W2, n);
    k_agg64<<<nb_a, 256>>>(b2, n, 1);
    // layer 3
    k_gemm<64, 4><<<nb_g, 256>>>(x, 0, W3, n);
    k_agg64<<<nb_a, 256>>>(b3, n, 1);
    // layer 4 (D_OUT = 16, no relu)
    k_gemm<16, 1><<<nb_g, 256>>>(x, 0, W4, n);
    k_agg16<<<nb_a, 256>>>(b4, out, n);
}

// round 6
// speedup vs baseline: 1.5908x; 1.0390x over previous
#include <cuda_runtime.h>
#include <cuda_fp16.h>
#include <cuda_bf16.h>
#include <cstdint>

#define NN 100000
#define EE 1600000

// ---------------- scratch (static device globals; no allocation) ----------
__device__ int   g_is64;
__device__ int   g_cnt[NN];
__device__ int   g_rowoff[NN + 1];
__device__ int   g_cursor[NN];
__device__ float g_dinv[NN];
__device__ int   g_bsum[128];
__device__ int   g_boff[128];
__device__ __align__(16) long long g_ew[EE];                 // packed (w<<32 | col)
__device__ __align__(16) __half    g_h16[(size_t)NN * 64];   // gemm out (fp16)
__device__ __align__(16) __half    g_a16[(size_t)NN * 64];   // agg out (fp16, gemm in)

// ---------------- small helpers ----------------------------------------
__device__ __forceinline__ void ffma2(unsigned long long& acc,
                                      unsigned long long a,
                                      unsigned long long b) {
    asm("fma.rn.f32x2 %0, %1, %2, %0;" : "+l"(acc) : "l"(a), "l"(b));
}
__device__ __forceinline__ unsigned long long pack_dup(float x) {
    unsigned long long r;
    asm("mov.b64 %0, {%1, %1};" : "=l"(r) : "f"(x));
    return r;
}
__device__ __forceinline__ float2 unpack2(unsigned long long v) {
    float2 f;
    asm("mov.b64 {%0, %1}, %2;" : "=f"(f.x), "=f"(f.y) : "l"(v));
    return f;
}

// ---------------- init: zero counters + dtype detection (block 0) -------
__global__ void k_init(const int* __restrict__ ei32, int n) {
    int i = blockIdx.x * blockDim.x + threadIdx.x;
    if (i < n) g_cnt[i] = 0;
    if (blockIdx.x == 0) {
        __shared__ int sor;
        if (threadIdx.x == 0) sor = 0;
        __syncthreads();
        int acc = 0;
        for (int k = threadIdx.x; k < 4096; k += blockDim.x)
            acc |= ei32[2 * k + 1];
        atomicOr(&sor, acc);
        __syncthreads();
        if (threadIdx.x == 0) g_is64 = (sor == 0) ? 1 : 0;
    }
}

__device__ __forceinline__ int edge_id(const void* ei, size_t idx) {
    if (g_is64) return (int)((const long long*)ei)[idx];
    return ((const int*)ei)[idx];
}

__global__ void k_count(const void* __restrict__ ei, int E) {
    int e = blockIdx.x * blockDim.x + threadIdx.x;
    if (e < E) atomicAdd(&g_cnt[edge_id(ei, (size_t)E + e)], 1);
}

// pass 1: per-block inclusive scan of cnt (1024/block), dinv fused
__global__ void k_scan1(int n) {
    __shared__ int wsum[32];
    int tid = threadIdx.x, lane = tid & 31, wid = tid >> 5;
    int i = blockIdx.x * 1024 + tid;
    int v = (i < n) ? g_cnt[i] : 0;
    if (i < n) g_dinv[i] = rsqrtf((float)(v + 1));  // +1 self loop
    int x = v;
    #pragma unroll
    for (int d = 1; d < 32; d <<= 1) {
        int t = __shfl_up_sync(0xffffffffu, x, d);
        if (lane >= d) x += t;
    }
    if (lane == 31) wsum[wid] = x;
    __syncthreads();
    if (wid == 0) {
        int y = wsum[lane];
        #pragma unroll
        for (int d = 1; d < 32; d <<= 1) {
            int t = __shfl_up_sync(0xffffffffu, y, d);
            if (lane >= d) y += t;
        }
        wsum[lane] = y;
    }
    __syncthreads();
    int incl = x + ((wid > 0) ? wsum[wid - 1] : 0);
    if (i < n) g_cursor[i] = incl;
    if (tid == 1023) g_bsum[blockIdx.x] = incl;
}

// pass 2: exclusive scan of <=128 block sums
__global__ void k_scan2(int nb) {
    __shared__ int ws[4];
    __shared__ int woff[4];
    int tid = threadIdx.x, lane = tid & 31, wid = tid >> 5;
    int v = (tid < nb) ? g_bsum[tid] : 0;
    int x = v;
    #pragma unroll
    for (int d = 1; d < 32; d <<= 1) {
        int t = __shfl_up_sync(0xffffffffu, x, d);
        if (lane >= d) x += t;
    }
    if (lane == 31) ws[wid] = x;
    __syncthreads();
    if (tid == 0) {
        int s = 0;
        #pragma unroll
        for (int w = 0; w < 4; w++) { woff[w] = s; s += ws[w]; }
    }
    __syncthreads();
    if (tid < nb) g_boff[tid] = x - v + woff[wid];
}

// pass 3: add block offsets -> rowoff / cursor
__global__ void k_scan3(int n) {
    int i = blockIdx.x * blockDim.x + threadIdx.x;
    if (i < n) {
        int incl = g_cursor[i] + g_boff[i >> 10];
        g_rowoff[i + 1] = incl;
        g_cursor[i]     = incl - g_cnt[i];
    }
    if (i == 0) g_rowoff[0] = 0;
}

__global__ void k_fill(const void* __restrict__ ei, int E) {
    int e = blockIdx.x * blockDim.x + threadIdx.x;
    if (e < E) {
        int s = edge_id(ei, (size_t)e);
        int d = edge_id(ei, (size_t)E + e);
        int j = atomicAdd(&g_cursor[d], 1);
        float w = g_dinv[s] * g_dinv[d];
        g_ew[j] = ((long long)((unsigned long long)__float_as_uint(w) << 32))
                | (long long)(unsigned)s;
    }
}

// ---------------- dense transform: g_h16 = (X @ W) as fp16 --------------
// use_ext=1: read fp32 external x.  use_ext=0: read fp16 g_a16 (device symbol).
template <int DOUT, int R>
__global__ void k_gemm(const float* __restrict__ x_ext, int use_ext,
                       const float* __restrict__ Wg, int n) {
    constexpr int COLG = DOUT / 4;        // 4-col groups per thread
    constexpr int TY   = 256 / COLG;
    constexpr int ROWS = TY * R;          // = 64
    __shared__ __align__(16) float Ws[64 * DOUT];
    __shared__ __align__(16) float Xs[ROWS][64];

    int tid = threadIdx.x;
    for (int i = tid; i < 64 * DOUT / 4; i += 256)
        ((float4*)Ws)[i] = ((const float4*)Wg)[i];

    int row0 = blockIdx.x * ROWS;
    for (int i = tid; i < ROWS * 16; i += 256) {
        int r = i >> 4, q = i & 15;
        int row = row0 + r;
        float4 f = make_float4(0.f, 0.f, 0.f, 0.f);
        if (row < n) {
            if (use_ext) {
                f = ((const float4*)x_ext)[(size_t)row * 16 + q];
            } else {
                uint2 v = ((const uint2*)g_a16)[(size_t)row * 16 + q];
                float2 f0 = __half22float2(*(const __half2*)&v.x);
                float2 f1 = __half22float2(*(const __half2*)&v.y);
                f = make_float4(f0.x, f0.y, f1.x, f1.y);
            }
        }
        *(float4*)&Xs[r][q * 4] = f;
    }
    __syncthreads();

    int tx = tid % COLG;
    int ty = tid / COLG;
    unsigned long long a01[R], a23[R];
    #pragma unroll
    for (int r = 0; r < R; r++) { a01[r] = 0ull; a23[r] = 0ull; }

    #pragma unroll
    for (int k4 = 0; k4 < 16; k4++) {
        float4 xv[R];
        #pragma unroll
        for (int r = 0; r < R; r++)
            xv[r] = *(const float4*)&Xs[ty * R + r][k4 * 4];
        #pragma unroll
        for (int kk = 0; kk < 4; kk++) {
            ulonglong2 wv = *(const ulonglong2*)&Ws[(k4 * 4 + kk) * DOUT + tx * 4];
            #pragma unroll
            for (int r = 0; r < R; r++) {
                float xs = (kk == 0) ? xv[r].x : (kk == 1) ? xv[r].y
                         : (kk == 2) ? xv[r].z : xv[r].w;
                unsigned long long xx = pack_dup(xs);
                ffma2(a01[r], xx, wv.x);
                ffma2(a23[r], xx, wv.y);
            }
        }
    }

    uint2* __restrict__ Y = (uint2*)g_h16;
    #pragma unroll
    for (int r = 0; r < R; r++) {
        int row = row0 + ty * R + r;
        if (row < n) {
            float2 f01 = unpack2(a01[r]);
            float2 f23 = unpack2(a23[r]);
            __half2 h0 = __floats2half2_rn(f01.x, f01.y);
            __half2 h1 = __floats2half2_rn(f23.x, f23.y);
            uint2 o;
            o.x = *(unsigned*)&h0;
            o.y = *(unsigned*)&h1;
            Y[(size_t)row * COLG + tx] = o;
        }
    }
}

// ---------------- aggregation: paired-edge gather, warp per node --------
// 16 lanes per edge, 8B (4 fp16 feats) per lane; 2 edges per warp-LDG.
// Reads g_h16 + CSR, writes g_a16 (fp16). 2 independent streams for MLP.
__global__ void k_agg64(const float* __restrict__ bias, int n, int relu) {
    int warp = (blockIdx.x * blockDim.x + threadIdx.x) >> 5;
    int lane = threadIdx.x & 31;
    if (warp >= n) return;
    int half = lane >> 4;      // which edge of the pair
    int sub  = lane & 15;      // feature quad 0..15
    int beg = g_rowoff[warp];
    int end = g_rowoff[warp + 1];
    const uint2* __restrict__ Hv = (const uint2*)g_h16;

    float4 acc  = make_float4(0.f, 0.f, 0.f, 0.f);
    float4 acc2 = make_float4(0.f, 0.f, 0.f, 0.f);

    // self loop on half-0 lanes
    if (half == 0) {
        float di = g_dinv[warp];
        float dd = di * di;
        uint2 hv = Hv[(size_t)warp * 16 + sub];
        float2 p0 = __half22float2(*(const __half2*)&hv.x);
        float2 p1 = __half22float2(*(const __half2*)&hv.y);
        acc.x = dd * p0.x; acc.y = dd * p0.y; acc.z = dd * p1.x; acc.w = dd * p1.y;
    }

    for (int j = beg; j < end; j += 4) {
        int j0 = j + half;
        int j1 = j + 2 + half;
        long long e0 = g_ew[min(j0, end - 1)];
        long long e1 = g_ew[min(j1, end - 1)];
        int   c0 = (int)(unsigned)(e0 & 0xffffffffLL);
        int   c1 = (int)(unsigned)(e1 & 0xffffffffLL);
        float w0 = (j0 < end) ? __uint_as_float((unsigned)((unsigned long long)e0 >> 32)) : 0.f;
        float w1 = (j1 < end) ? __uint_as_float((unsigned)((unsigned long long)e1 >> 32)) : 0.f;
        uint2 v0 = Hv[(size_t)c0 * 16 + sub];
        uint2 v1 = Hv[(size_t)c1 * 16 + sub];
        float2 p00 = __half22float2(*(const __half2*)&v0.x);
        float2 p01 = __half22float2(*(const __half2*)&v0.y);
        float2 p10 = __half22float2(*(const __half2*)&v1.x);
        float2 p11 = __half22float2(*(const __half2*)&v1.y);
        acc.x  += w0 * p00.x;  acc.y  += w0 * p00.y;
        acc.z  += w0 * p01.x;  acc.w  += w0 * p01.y;
        acc2.x += w1 * p10.x;  acc2.y += w1 * p10.y;
        acc2.z += w1 * p11.x;  acc2.w += w1 * p11.y;
    }
    acc.x += acc2.x; acc.y += acc2.y; acc.z += acc2.z; acc.w += acc2.w;

    // combine the two edge-halves (lanes 16-31 -> lanes 0-15)
    acc.x += __shfl_down_sync(0xffffffffu, acc.x, 16);
    acc.y += __shfl_down_sync(0xffffffffu, acc.y, 16);
    acc.z += __shfl_down_sync(0xffffffffu, acc.z, 16);
    acc.w += __shfl_down_sync(0xffffffffu, acc.w, 16);

    if (lane < 16) {
        float4 b4 = ((const float4*)bias)[sub];
        acc.x += b4.x; acc.y += b4.y; acc.z += b4.z; acc.w += b4.w;
        if (relu) {
            acc.x = fmaxf(acc.x, 0.f); acc.y = fmaxf(acc.y, 0.f);
            acc.z = fmaxf(acc.z, 0.f); acc.w = fmaxf(acc.w, 0.f);
        }
        __half2 h0 = __floats2half2_rn(acc.x, acc.y);
        __half2 h1 = __floats2half2_rn(acc.z, acc.w);
        uint2 o;
        o.x = *(unsigned*)&h0;
        o.y = *(unsigned*)&h1;
        ((uint2*)g_a16)[(size_t)warp * 16 + sub] = o;
    }
}

// D=16 final layer: warp per node, 4 edges in flight (8 lanes per edge)
__global__ void k_agg16(const float* __restrict__ bias, float* __restrict__ out, int n) {
    int warp = (blockIdx.x * blockDim.x + threadIdx.x) >> 5;
    int lane = threadIdx.x & 31;
    if (warp >= n) return;
    int eg = lane >> 3;        // edge group 0..3
    int p  = lane & 7;         // feature pair 0..7
    int beg = g_rowoff[warp];
    int end = g_rowoff[warp + 1];
    const __half2* __restrict__ H = (const __half2*)g_h16;

    float di = g_dinv[warp];
    float dd = di * di;
    float2 acc = make_float2(0.f, 0.f);
    if (eg == 0) {
        float2 hv = __half22float2(H[(size_t)warp * 8 + p]);
        acc.x = dd * hv.x;  acc.y = dd * hv.y;
    }
    for (int j = beg + eg; j < end; j += 4) {
        long long e = g_ew[j];
        int   c = (int)(unsigned)(e & 0xffffffffLL);
        float w = __uint_as_float((unsigned)((unsigned long long)e >> 32));
        float2 v = __half22float2(H[(size_t)c * 8 + p]);
        acc.x += w * v.x;  acc.y += w * v.y;
    }
    acc.x += __shfl_xor_sync(0xffffffffu, acc.x, 8);
    acc.x += __shfl_xor_sync(0xffffffffu, acc.x, 16);
    acc.y += __shfl_xor_sync(0xffffffffu, acc.y, 8);
    acc.y += __shfl_xor_sync(0xffffffffu, acc.y, 16);

    if (lane < 8) {
        float2 b2 = ((const float2*)bias)[p];
        ((float2*)out)[(size_t)warp * 8 + p] = make_float2(acc.x + b2.x, acc.y + b2.y);
    }
}

// ---------------- launch ------------------------------------------------
extern "C" void kernel_launch(void* const* d_in, const int* in_sizes, int n_in,
                              void* d_out, int out_size) {
    const float* x  = (const float*)d_in[0];
    const void*  ei = d_in[1];
    const float* W1 = (const float*)d_in[2];  const float* b1 = (const float*)d_in[3];
    const float* W2 = (const float*)d_in[4];  const float* b2 = (const float*)d_in[5];
    const float* W3 = (const float*)d_in[6];  const float* b3 = (const float*)d_in[7];
    const float* W4 = (const float*)d_in[8];  const float* b4 = (const float*)d_in[9];
    float* out = (float*)d_out;

    int n = in_sizes[0] / 64;   // 100000
    int E = in_sizes[1] / 2;    // 1600000

    int nb_n  = (n + 255) / 256;
    int nb_e  = (E + 255) / 256;
    int nb_s1 = (n + 1023) / 1024;            // <=128
    int nb_g  = (n + 63) / 64;
    int nb_a  = ((n * 32) + 255) / 256;

    // CSR build
    k_init<<<nb_n, 256>>>((const int*)ei, n);
    k_count<<<nb_e, 256>>>(ei, E);
    k_scan1<<<nb_s1, 1024>>>(n);
    k_scan2<<<1, 128>>>(nb_s1);
    k_scan3<<<nb_n, 256>>>(n);
    k_fill<<<nb_e, 256>>>(ei, E);

    // layer 1 (fp32 input)
    k_gemm<64, 4><<<nb_g, 256>>>(x, 1, W1, n);
    k_agg64<<<nb_a, 256>>>(b1, n, 1);
    // layers 2-3 (fp16 input from g_a16, selected device-side)
    k_gemm<64, 4><<<nb_g, 256>>>(x, 0, W2, n);
    k_agg64<<<nb_a, 256>>>(b2, n, 1);
    k_gemm<64, 4><<<nb_g, 256>>>(x, 0, W3, n);
    k_agg64<<<nb_a, 256>>>(b3, n, 1);
    // layer 4 (D_OUT = 16, no relu)
    k_gemm<16, 1><<<nb_g, 256>>>(x, 0, W4, n);
    k_agg16<<<nb_a, 256>>>(b4, out, n);
}